// round 6
// baseline (speedup 1.0000x reference)
#include <cuda_runtime.h>
#include <cuda_fp16.h>
#include <cstdint>
#include <math.h>

#define EPSF 1e-5f

static const int N_TOK = 16384;   // B*T = 8*2048
static const int DIM   = 1024;
static const int FF    = 4096;

// ---------------- scratch (device globals; allocation-free) ----------------
__device__ __half   g_w1h[(size_t)FF * DIM];      // 8 MB  (quantized ints as half)
__device__ __half   g_w2h[(size_t)DIM * FF];      // 8 MB
__device__ __half   g_a1h[(size_t)N_TOK * DIM];   // 32 MB
__device__ __half   g_a2h[(size_t)N_TOK * FF];    // 128 MB
__device__ float    g_h  [(size_t)N_TOK * FF];    // 256 MB
__device__ float    g_dqa1[N_TOK];
__device__ unsigned g_hmax[N_TOK];                // float bits, idempotent max
__device__ unsigned g_wmax[2];                    // float bits

// ---------------- small PTX helpers ----------------
__device__ __forceinline__ void cp16(uint32_t dst, const void* src) {
    asm volatile("cp.async.cg.shared.global [%0], [%1], 16;\n" :: "r"(dst), "l"(src));
}
__device__ __forceinline__ void cp_commit() { asm volatile("cp.async.commit_group;\n"); }
template<int N> __device__ __forceinline__ void cp_wait() {
    asm volatile("cp.async.wait_group %0;\n" :: "n"(N));
}
__device__ __forceinline__ void ldsm4(uint32_t& r0, uint32_t& r1, uint32_t& r2, uint32_t& r3,
                                      uint32_t addr) {
    asm volatile("ldmatrix.sync.aligned.m8n8.x4.shared.b16 {%0,%1,%2,%3}, [%4];"
                 : "=r"(r0), "=r"(r1), "=r"(r2), "=r"(r3) : "r"(addr));
}

// ======================= fp16 GEMM via mma.sync m16n8k16 =======================
// Operands are quantized integers stored as fp16 (exact); accumulate fp32.
// BM=128, BN=256, BK=64 (128B rows). 256 threads = 8 warps as 2(m) x 4(n),
// warp tile 64x64. 4-stage cp.async pipeline (192KB smem, 1 CTA/SM).
// Smem swizzle: 16B chunk' = chunk ^ (row & 7)  (8 chunks per 128B row).
//
// EPI==1: g_h = swish(dq(a1 @ w1^T) + b1), row absmax -> g_hmax
// EPI==2: out = x + 0.5*mask*(dq(a2 @ w2^T) + b2)
template<int EPI>
__launch_bounds__(256, 1)
__global__ void gemm_f16_k(const float* __restrict__ bias,
                           const float* __restrict__ xres,
                           const float* __restrict__ mask,
                           float* __restrict__ out) {
    constexpr int K  = (EPI == 1) ? DIM : FF;        // elements (halves)
    constexpr int KT = K / 64;                       // BK=64 slabs
    constexpr int STAGE = 128 * 128 + 256 * 128;     // A 16KB + B 32KB = 48KB

    const __half* __restrict__ A  = (EPI == 1) ? g_a1h : g_a2h;
    const __half* __restrict__ Bw = (EPI == 1) ? g_w1h : g_w2h;

    extern __shared__ int8_t sm[];                   // 4 * 48KB

    const int tid  = threadIdx.x;
    const int lane = tid & 31;
    const int warp = tid >> 5;
    const int wm   = warp >> 2;                      // 0..1
    const int wn   = warp & 3;                       // 0..3
    const int bm   = blockIdx.y * 128;
    const int bn   = blockIdx.x * 256;

    float acc[4][8][4];
    #pragma unroll
    for (int mi = 0; mi < 4; mi++)
        #pragma unroll
        for (int ni = 0; ni < 8; ni++)
            #pragma unroll
            for (int j = 0; j < 4; j++) acc[mi][ni][j] = 0.f;

    auto ld_stage = [&](int stg, int kt) {
        uint32_t ab = (uint32_t)__cvta_generic_to_shared(sm + stg * STAGE);
        uint32_t bb = ab + 128 * 128;
        #pragma unroll
        for (int i = 0; i < 4; i++) {                // A: 1024 chunks of 16B
            int c = tid + i * 256;
            int row = c >> 3, ch = c & 7;
            uint32_t dst = ab + row * 128 + ((ch ^ (row & 7)) << 4);
            cp16(dst, (const int8_t*)A + (size_t)(bm + row) * (K * 2) + kt * 128 + ch * 16);
        }
        #pragma unroll
        for (int i = 0; i < 8; i++) {                // B: 2048 chunks of 16B
            int c = tid + i * 256;
            int row = c >> 3, ch = c & 7;
            uint32_t dst = bb + row * 128 + ((ch ^ (row & 7)) << 4);
            cp16(dst, (const int8_t*)Bw + (size_t)(bn + row) * (K * 2) + kt * 128 + ch * 16);
        }
        cp_commit();
    };

    ld_stage(0, 0);
    ld_stage(1, 1);
    ld_stage(2, 2);

    for (int kt = 0; kt < KT; ++kt) {
        if      (kt + 3 < KT) { cp_wait<2>(); }
        else if (kt + 2 < KT) { cp_wait<1>(); }
        else                  { cp_wait<0>(); }
        __syncthreads();
        if (kt + 3 < KT) ld_stage((kt + 3) & 3, kt + 3);

        uint32_t abase = (uint32_t)__cvta_generic_to_shared(sm + (kt & 3) * STAGE);
        uint32_t bbase = abase + 128 * 128;

        #pragma unroll
        for (int ks = 0; ks < 4; ++ks) {             // four k16 steps per slab
            uint32_t af[4][4], bf[8][2];
            #pragma unroll
            for (int mi = 0; mi < 4; mi++) {
                int row = wm * 64 + mi * 16 + (lane & 15);
                int ch  = 2 * ks + (lane >> 4);
                uint32_t a = abase + row * 128 + ((ch ^ (row & 7)) << 4);
                ldsm4(af[mi][0], af[mi][1], af[mi][2], af[mi][3], a);
            }
            #pragma unroll
            for (int p = 0; p < 4; p++) {
                int row = wn * 64 + p * 16 + ((lane >> 4) << 3) + (lane & 7);
                int ch  = 2 * ks + ((lane >> 3) & 1);
                uint32_t a = bbase + row * 128 + ((ch ^ (row & 7)) << 4);
                ldsm4(bf[2 * p][0], bf[2 * p][1], bf[2 * p + 1][0], bf[2 * p + 1][1], a);
            }
            #pragma unroll
            for (int mi = 0; mi < 4; mi++)
                #pragma unroll
                for (int ni = 0; ni < 8; ni++)
                    asm volatile(
                        "mma.sync.aligned.m16n8k16.row.col.f32.f16.f16.f32 "
                        "{%0,%1,%2,%3}, {%4,%5,%6,%7}, {%8,%9}, {%0,%1,%2,%3};\n"
                        : "+f"(acc[mi][ni][0]), "+f"(acc[mi][ni][1]),
                          "+f"(acc[mi][ni][2]), "+f"(acc[mi][ni][3])
                        : "r"(af[mi][0]), "r"(af[mi][1]), "r"(af[mi][2]), "r"(af[mi][3]),
                          "r"(bf[ni][0]), "r"(bf[ni][1]));
        }
    }

    // ---------------- epilogue (8-warp 2x4 mapping, proven in R4) ----------------
    const float dqw = fmaxf(__uint_as_float(g_wmax[EPI - 1]), EPSF) * (1.f / 127.f);

    if (EPI == 1) {
        #pragma unroll
        for (int mi = 0; mi < 4; mi++) {
            #pragma unroll
            for (int half = 0; half < 2; ++half) {
                int row = bm + wm * 64 + mi * 16 + (lane >> 2) + half * 8;
                float f = g_dqa1[row] * dqw;
                float rmax = 0.f;
                #pragma unroll
                for (int ni = 0; ni < 8; ni++) {
                    #pragma unroll
                    for (int j = 0; j < 2; j++) {
                        int col = bn + wn * 64 + ni * 8 + (lane & 3) * 2 + j;
                        float v  = acc[mi][ni][half * 2 + j] * f + __ldg(&bias[col]);
                        float hv = v / (1.f + __expf(-v));     // v * sigmoid(v)
                        g_h[(size_t)row * FF + col] = hv;
                        rmax = fmaxf(rmax, fabsf(hv));
                    }
                }
                rmax = fmaxf(rmax, __shfl_xor_sync(0xffffffffu, rmax, 1));
                rmax = fmaxf(rmax, __shfl_xor_sync(0xffffffffu, rmax, 2));
                if ((lane & 3) == 0) atomicMax(&g_hmax[row], __float_as_uint(rmax));
            }
        }
    } else {
        #pragma unroll
        for (int mi = 0; mi < 4; mi++) {
            #pragma unroll
            for (int half = 0; half < 2; ++half) {
                int row = bm + wm * 64 + mi * 16 + (lane >> 2) + half * 8;
                float f  = fmaxf(__uint_as_float(g_hmax[row]), EPSF) * (1.f / 127.f) * dqw;
                float mk = mask[row];
                #pragma unroll
                for (int ni = 0; ni < 8; ni++) {
                    #pragma unroll
                    for (int j = 0; j < 2; j++) {
                        int col = bn + wn * 64 + ni * 8 + (lane & 3) * 2 + j;
                        float v = acc[mi][ni][half * 2 + j] * f + __ldg(&bias[col]);
                        out[(size_t)row * DIM + col] =
                            xres[(size_t)row * DIM + col] + 0.5f * v * mk;
                    }
                }
            }
        }
    }
}

// ======================= elementwise kernels =======================
template<int WI>
__global__ void absmax_k(const float4* __restrict__ x, int n4) {
    float m = 0.f;
    for (int i = blockIdx.x * blockDim.x + threadIdx.x; i < n4; i += gridDim.x * blockDim.x) {
        float4 v = x[i];
        m = fmaxf(m, fmaxf(fmaxf(fabsf(v.x), fabsf(v.y)), fmaxf(fabsf(v.z), fabsf(v.w))));
    }
    #pragma unroll
    for (int o = 16; o; o >>= 1) m = fmaxf(m, __shfl_xor_sync(0xffffffffu, m, o));
    __shared__ float sh[32];
    if ((threadIdx.x & 31) == 0) sh[threadIdx.x >> 5] = m;
    __syncthreads();
    if (threadIdx.x < 32) {
        m = (threadIdx.x < (blockDim.x >> 5)) ? sh[threadIdx.x] : 0.f;
        #pragma unroll
        for (int o = 16; o; o >>= 1) m = fmaxf(m, __shfl_xor_sync(0xffffffffu, m, o));
        if (threadIdx.x == 0) atomicMax(&g_wmax[WI], __float_as_uint(m));
    }
}

template<int WI>
__global__ void quantw_k(const float4* __restrict__ w, int n4) {
    int i = blockIdx.x * blockDim.x + threadIdx.x;
    if (i >= n4) return;
    float s = 127.f / fmaxf(__uint_as_float(g_wmax[WI]), EPSF);
    float4 v = w[i];
    __half2 h0 = __floats2half2_rn(rintf(fminf(fmaxf(v.x * s, -127.f), 127.f)),
                                   rintf(fminf(fmaxf(v.y * s, -127.f), 127.f)));
    __half2 h1 = __floats2half2_rn(rintf(fminf(fmaxf(v.z * s, -127.f), 127.f)),
                                   rintf(fminf(fmaxf(v.w * s, -127.f), 127.f)));
    __half2* dst = (__half2*)(WI == 0 ? g_w1h : g_w2h);
    dst[2 * i]     = h0;
    dst[2 * i + 1] = h1;
}

__global__ void ln_quant_k(const float4* __restrict__ x,
                           const float4* __restrict__ gamma,
                           const float4* __restrict__ beta) {
    const int row = blockIdx.x;
    const int t   = threadIdx.x;           // 256 threads, D/4 = 256 float4
    __shared__ float sh[8];

    float4 v = x[(size_t)row * 256 + t];
    float s = v.x + v.y + v.z + v.w;
    #pragma unroll
    for (int o = 16; o; o >>= 1) s += __shfl_xor_sync(0xffffffffu, s, o);
    if ((t & 31) == 0) sh[t >> 5] = s;
    __syncthreads();
    float mu = sh[0];
    #pragma unroll
    for (int i = 1; i < 8; i++) mu += sh[i];
    mu *= (1.f / 1024.f);
    __syncthreads();

    float d0 = v.x - mu, d1 = v.y - mu, d2 = v.z - mu, d3 = v.w - mu;
    float ss = d0*d0 + d1*d1 + d2*d2 + d3*d3;
    #pragma unroll
    for (int o = 16; o; o >>= 1) ss += __shfl_xor_sync(0xffffffffu, ss, o);
    if ((t & 31) == 0) sh[t >> 5] = ss;
    __syncthreads();
    float var = sh[0];
    #pragma unroll
    for (int i = 1; i < 8; i++) var += sh[i];
    var *= (1.f / 1024.f);
    __syncthreads();

    float rstd = rsqrtf(var + EPSF);
    float4 g = gamma[t], b = beta[t];
    float y0 = d0 * rstd * g.x + b.x;
    float y1 = d1 * rstd * g.y + b.y;
    float y2 = d2 * rstd * g.z + b.z;
    float y3 = d3 * rstd * g.w + b.w;

    float am = fmaxf(fmaxf(fabsf(y0), fabsf(y1)), fmaxf(fabsf(y2), fabsf(y3)));
    #pragma unroll
    for (int o = 16; o; o >>= 1) am = fmaxf(am, __shfl_xor_sync(0xffffffffu, am, o));
    if ((t & 31) == 0) sh[t >> 5] = am;
    __syncthreads();
    float amax = sh[0];
    #pragma unroll
    for (int i = 1; i < 8; i++) amax = fmaxf(amax, sh[i]);

    amax = fmaxf(amax, EPSF);
    float sc = 127.f / amax;
    __half2 h0 = __floats2half2_rn(rintf(fminf(fmaxf(y0 * sc, -127.f), 127.f)),
                                   rintf(fminf(fmaxf(y1 * sc, -127.f), 127.f)));
    __half2 h1 = __floats2half2_rn(rintf(fminf(fmaxf(y2 * sc, -127.f), 127.f)),
                                   rintf(fminf(fmaxf(y3 * sc, -127.f), 127.f)));
    __half2* dst = (__half2*)g_a1h;
    dst[(size_t)row * 512 + 2 * t]     = h0;
    dst[(size_t)row * 512 + 2 * t + 1] = h1;
    if (t == 0) g_dqa1[row] = amax * (1.f / 127.f);
}

// 2 float4 per thread (32B) for MLP; coalesced per-warp 1KB segments.
__global__ void quant_h_k() {
    size_t gid = (size_t)blockIdx.x * blockDim.x + threadIdx.x;
    size_t i = gid * 2;
    const float4* __restrict__ src = (const float4*)g_h;
    __half2* __restrict__ dst = (__half2*)g_a2h;
    #pragma unroll
    for (int u = 0; u < 2; u++) {
        size_t idx = i + u;
        int row = (int)(idx >> 10);                  // FF/4 = 1024 float4 per row
        float s = 127.f / fmaxf(__uint_as_float(g_hmax[row]), EPSF);
        float4 v = src[idx];
        __half2 h0 = __floats2half2_rn(rintf(fminf(fmaxf(v.x * s, -127.f), 127.f)),
                                       rintf(fminf(fmaxf(v.y * s, -127.f), 127.f)));
        __half2 h1 = __floats2half2_rn(rintf(fminf(fmaxf(v.z * s, -127.f), 127.f)),
                                       rintf(fminf(fmaxf(v.w * s, -127.f), 127.f)));
        dst[2 * idx]     = h0;
        dst[2 * idx + 1] = h1;
    }
}

// ======================= launcher =======================
extern "C" void kernel_launch(void* const* d_in, const int* in_sizes, int n_in,
                              void* d_out, int out_size) {
    const float* x     = (const float*)d_in[0];   // [8,2048,1024]
    const float* mask  = (const float*)d_in[1];   // [8,2048,1]
    const float* gamma = (const float*)d_in[2];   // [1024]
    const float* beta  = (const float*)d_in[3];   // [1024]
    const float* w1    = (const float*)d_in[4];   // [4096,1024]
    const float* b1    = (const float*)d_in[5];   // [4096]
    const float* w2    = (const float*)d_in[6];   // [1024,4096]
    const float* b2    = (const float*)d_in[7];   // [1024]
    float* out = (float*)d_out;

    const int wn4 = (FF * DIM) / 4;
    const int GEMM_SMEM = 4 * (128 * 128 + 256 * 128);   // 196608 = 192KB
    cudaFuncSetAttribute(gemm_f16_k<1>, cudaFuncAttributeMaxDynamicSharedMemorySize, GEMM_SMEM);
    cudaFuncSetAttribute(gemm_f16_k<2>, cudaFuncAttributeMaxDynamicSharedMemorySize, GEMM_SMEM);

    // weights: absmax -> quantize to fp16 ints (idempotent across graph replays)
    absmax_k<0><<<2048, 256>>>((const float4*)w1, wn4);
    absmax_k<1><<<2048, 256>>>((const float4*)w2, wn4);
    quantw_k<0><<<wn4 / 256, 256>>>((const float4*)w1, wn4);
    quantw_k<1><<<wn4 / 256, 256>>>((const float4*)w2, wn4);

    // LN + per-token act quant -> fp16 ints
    ln_quant_k<<<N_TOK, 256>>>((const float4*)x, (const float4*)gamma, (const float4*)beta);

    // GEMM1 + swish + row absmax
    gemm_f16_k<1><<<dim3(FF / 256, N_TOK / 128), 256, GEMM_SMEM>>>(b1, nullptr, nullptr, nullptr);

    // quantize h -> fp16 ints
    quant_h_k<<<(N_TOK * (FF / 4)) / 512, 256>>>();

    // GEMM2 + residual
    gemm_f16_k<2><<<dim3(DIM / 256, N_TOK / 128), 256, GEMM_SMEM>>>(b2, x, mask, out);
}

// round 7
// speedup vs baseline: 1.1921x; 1.1921x over previous
#include <cuda_runtime.h>
#include <cuda_fp16.h>
#include <cstdint>
#include <math.h>

#define EPSF 1e-5f

static const int N_TOK = 16384;   // B*T = 8*2048
static const int DIM   = 1024;
static const int FF    = 4096;

// ---------------- scratch (device globals; allocation-free) ----------------
__device__ __half   g_w1h[(size_t)FF * DIM];      // 8 MB  (quantized ints as half)
__device__ __half   g_w2h[(size_t)DIM * FF];      // 8 MB
__device__ __half   g_a1h[(size_t)N_TOK * DIM];   // 32 MB
__device__ __half   g_a2h[(size_t)N_TOK * FF];    // 128 MB
__device__ float    g_h  [(size_t)N_TOK * FF];    // 256 MB
__device__ float    g_dqa1[N_TOK];
__device__ unsigned g_hmax[N_TOK];                // float bits, idempotent max
__device__ unsigned g_wmax[2];                    // float bits

// ---------------- small PTX helpers ----------------
__device__ __forceinline__ void cp16(uint32_t dst, const void* src) {
    asm volatile("cp.async.cg.shared.global [%0], [%1], 16;\n" :: "r"(dst), "l"(src));
}
__device__ __forceinline__ void cp_commit() { asm volatile("cp.async.commit_group;\n"); }
template<int N> __device__ __forceinline__ void cp_wait() {
    asm volatile("cp.async.wait_group %0;\n" :: "n"(N));
}
__device__ __forceinline__ void ldsm4(uint32_t& r0, uint32_t& r1, uint32_t& r2, uint32_t& r3,
                                      uint32_t addr) {
    asm volatile("ldmatrix.sync.aligned.m8n8.x4.shared.b16 {%0,%1,%2,%3}, [%4];"
                 : "=r"(r0), "=r"(r1), "=r"(r2), "=r"(r3) : "r"(addr));
}

// ======================= fp16 GEMM via mma.sync m16n8k16 =======================
// Operands are quantized integers stored as fp16 (exact); accumulate fp32.
// BM=128, BN=128, BK=64 (128B rows). 128 threads = 4 warps as 2(m) x 2(n),
// warp tile 64x64. 3-stage cp.async pipeline, 96KB smem/CTA, 2 CTAs/SM.
// Smem swizzle: 16B chunk' = chunk ^ (row & 7)  (8 chunks per 128B row).
//
// EPI==1: g_h = swish(dq(a1 @ w1^T) + b1), row absmax -> g_hmax
// EPI==2: out = x + 0.5*mask*(dq(a2 @ w2^T) + b2)
template<int EPI>
__launch_bounds__(128, 2)
__global__ void gemm_f16_k(const float* __restrict__ bias,
                           const float* __restrict__ xres,
                           const float* __restrict__ mask,
                           float* __restrict__ out) {
    constexpr int K  = (EPI == 1) ? DIM : FF;        // elements (halves)
    constexpr int KT = K / 64;                       // BK=64 slabs
    constexpr int STAGE = 128 * 128 * 2;             // A 16KB + B 16KB = 32KB

    const __half* __restrict__ A  = (EPI == 1) ? g_a1h : g_a2h;
    const __half* __restrict__ Bw = (EPI == 1) ? g_w1h : g_w2h;

    extern __shared__ int8_t sm[];                   // 3 * 32KB

    const int tid  = threadIdx.x;
    const int lane = tid & 31;
    const int warp = tid >> 5;
    const int wm   = warp >> 1;                      // 0..1
    const int wn   = warp & 1;                       // 0..1
    const int bm   = blockIdx.y * 128;
    const int bn   = blockIdx.x * 128;

    float acc[4][8][4];
    #pragma unroll
    for (int mi = 0; mi < 4; mi++)
        #pragma unroll
        for (int ni = 0; ni < 8; ni++)
            #pragma unroll
            for (int j = 0; j < 4; j++) acc[mi][ni][j] = 0.f;

    auto ld_stage = [&](int stg, int kt) {
        uint32_t ab = (uint32_t)__cvta_generic_to_shared(sm + stg * STAGE);
        uint32_t bb = ab + 128 * 128;
        #pragma unroll
        for (int i = 0; i < 8; i++) {                // A: 1024 chunks of 16B
            int c = tid + i * 128;
            int row = c >> 3, ch = c & 7;
            uint32_t dst = ab + row * 128 + ((ch ^ (row & 7)) << 4);
            cp16(dst, (const int8_t*)A + (size_t)(bm + row) * (K * 2) + kt * 128 + ch * 16);
        }
        #pragma unroll
        for (int i = 0; i < 8; i++) {                // B: 1024 chunks of 16B
            int c = tid + i * 128;
            int row = c >> 3, ch = c & 7;
            uint32_t dst = bb + row * 128 + ((ch ^ (row & 7)) << 4);
            cp16(dst, (const int8_t*)Bw + (size_t)(bn + row) * (K * 2) + kt * 128 + ch * 16);
        }
        cp_commit();
    };

    ld_stage(0, 0);
    ld_stage(1, 1);

    for (int kt = 0; kt < KT; ++kt) {
        if (kt + 2 < KT) { cp_wait<1>(); } else { cp_wait<0>(); }
        __syncthreads();
        if (kt + 2 < KT) ld_stage((kt + 2) % 3, kt + 2);

        uint32_t abase = (uint32_t)__cvta_generic_to_shared(sm + (kt % 3) * STAGE);
        uint32_t bbase = abase + 128 * 128;

        #pragma unroll
        for (int ks = 0; ks < 4; ++ks) {             // four k16 steps per slab
            uint32_t af[4][4], bf[8][2];
            #pragma unroll
            for (int mi = 0; mi < 4; mi++) {
                int row = wm * 64 + mi * 16 + (lane & 15);
                int ch  = 2 * ks + (lane >> 4);
                uint32_t a = abase + row * 128 + ((ch ^ (row & 7)) << 4);
                ldsm4(af[mi][0], af[mi][1], af[mi][2], af[mi][3], a);
            }
            #pragma unroll
            for (int p = 0; p < 4; p++) {
                int row = wn * 64 + p * 16 + ((lane >> 4) << 3) + (lane & 7);
                int ch  = 2 * ks + ((lane >> 3) & 1);
                uint32_t a = bbase + row * 128 + ((ch ^ (row & 7)) << 4);
                ldsm4(bf[2 * p][0], bf[2 * p][1], bf[2 * p + 1][0], bf[2 * p + 1][1], a);
            }
            #pragma unroll
            for (int mi = 0; mi < 4; mi++)
                #pragma unroll
                for (int ni = 0; ni < 8; ni++)
                    asm volatile(
                        "mma.sync.aligned.m16n8k16.row.col.f32.f16.f16.f32 "
                        "{%0,%1,%2,%3}, {%4,%5,%6,%7}, {%8,%9}, {%0,%1,%2,%3};\n"
                        : "+f"(acc[mi][ni][0]), "+f"(acc[mi][ni][1]),
                          "+f"(acc[mi][ni][2]), "+f"(acc[mi][ni][3])
                        : "r"(af[mi][0]), "r"(af[mi][1]), "r"(af[mi][2]), "r"(af[mi][3]),
                          "r"(bf[ni][0]), "r"(bf[ni][1]));
        }
    }

    // ---------------- epilogue (4-warp 2x2 mapping, proven in R5) ----------------
    const float dqw = fmaxf(__uint_as_float(g_wmax[EPI - 1]), EPSF) * (1.f / 127.f);

    if (EPI == 1) {
        #pragma unroll
        for (int mi = 0; mi < 4; mi++) {
            #pragma unroll
            for (int half = 0; half < 2; ++half) {
                int row = bm + wm * 64 + mi * 16 + (lane >> 2) + half * 8;
                float f = g_dqa1[row] * dqw;
                float rmax = 0.f;
                #pragma unroll
                for (int ni = 0; ni < 8; ni++) {
                    #pragma unroll
                    for (int j = 0; j < 2; j++) {
                        int col = bn + wn * 64 + ni * 8 + (lane & 3) * 2 + j;
                        float v  = acc[mi][ni][half * 2 + j] * f + __ldg(&bias[col]);
                        float hv = v / (1.f + __expf(-v));     // v * sigmoid(v)
                        g_h[(size_t)row * FF + col] = hv;
                        rmax = fmaxf(rmax, fabsf(hv));
                    }
                }
                rmax = fmaxf(rmax, __shfl_xor_sync(0xffffffffu, rmax, 1));
                rmax = fmaxf(rmax, __shfl_xor_sync(0xffffffffu, rmax, 2));
                if ((lane & 3) == 0) atomicMax(&g_hmax[row], __float_as_uint(rmax));
            }
        }
    } else {
        #pragma unroll
        for (int mi = 0; mi < 4; mi++) {
            #pragma unroll
            for (int half = 0; half < 2; ++half) {
                int row = bm + wm * 64 + mi * 16 + (lane >> 2) + half * 8;
                float f  = fmaxf(__uint_as_float(g_hmax[row]), EPSF) * (1.f / 127.f) * dqw;
                float mk = mask[row];
                #pragma unroll
                for (int ni = 0; ni < 8; ni++) {
                    #pragma unroll
                    for (int j = 0; j < 2; j++) {
                        int col = bn + wn * 64 + ni * 8 + (lane & 3) * 2 + j;
                        float v = acc[mi][ni][half * 2 + j] * f + __ldg(&bias[col]);
                        out[(size_t)row * DIM + col] =
                            xres[(size_t)row * DIM + col] + 0.5f * v * mk;
                    }
                }
            }
        }
    }
}

// ======================= elementwise kernels =======================
// Both weights in one launch: blockIdx.y selects tensor.
__global__ void absmax_both_k(const float4* __restrict__ w1,
                              const float4* __restrict__ w2, int n4) {
    const int wi = blockIdx.y;
    const float4* __restrict__ x = wi ? w2 : w1;
    float m = 0.f;
    for (int i = blockIdx.x * blockDim.x + threadIdx.x; i < n4; i += gridDim.x * blockDim.x) {
        float4 v = x[i];
        m = fmaxf(m, fmaxf(fmaxf(fabsf(v.x), fabsf(v.y)), fmaxf(fabsf(v.z), fabsf(v.w))));
    }
    #pragma unroll
    for (int o = 16; o; o >>= 1) m = fmaxf(m, __shfl_xor_sync(0xffffffffu, m, o));
    __shared__ float sh[32];
    if ((threadIdx.x & 31) == 0) sh[threadIdx.x >> 5] = m;
    __syncthreads();
    if (threadIdx.x < 32) {
        m = (threadIdx.x < (blockDim.x >> 5)) ? sh[threadIdx.x] : 0.f;
        #pragma unroll
        for (int o = 16; o; o >>= 1) m = fmaxf(m, __shfl_xor_sync(0xffffffffu, m, o));
        if (threadIdx.x == 0) atomicMax(&g_wmax[wi], __float_as_uint(m));
    }
}

__global__ void quantw_both_k(const float4* __restrict__ w1,
                              const float4* __restrict__ w2, int n4) {
    const int wi = blockIdx.y;
    const float4* __restrict__ w = wi ? w2 : w1;
    int i = blockIdx.x * blockDim.x + threadIdx.x;
    if (i >= n4) return;
    float s = 127.f / fmaxf(__uint_as_float(g_wmax[wi]), EPSF);
    float4 v = w[i];
    __half2 h0 = __floats2half2_rn(rintf(fminf(fmaxf(v.x * s, -127.f), 127.f)),
                                   rintf(fminf(fmaxf(v.y * s, -127.f), 127.f)));
    __half2 h1 = __floats2half2_rn(rintf(fminf(fmaxf(v.z * s, -127.f), 127.f)),
                                   rintf(fminf(fmaxf(v.w * s, -127.f), 127.f)));
    __half2* dst = (__half2*)(wi ? g_w2h : g_w1h);
    dst[2 * i]     = h0;
    dst[2 * i + 1] = h1;
}

__global__ void ln_quant_k(const float4* __restrict__ x,
                           const float4* __restrict__ gamma,
                           const float4* __restrict__ beta) {
    const int row = blockIdx.x;
    const int t   = threadIdx.x;           // 256 threads, D/4 = 256 float4
    __shared__ float sh[8];

    float4 v = x[(size_t)row * 256 + t];
    float s = v.x + v.y + v.z + v.w;
    #pragma unroll
    for (int o = 16; o; o >>= 1) s += __shfl_xor_sync(0xffffffffu, s, o);
    if ((t & 31) == 0) sh[t >> 5] = s;
    __syncthreads();
    float mu = sh[0];
    #pragma unroll
    for (int i = 1; i < 8; i++) mu += sh[i];
    mu *= (1.f / 1024.f);
    __syncthreads();

    float d0 = v.x - mu, d1 = v.y - mu, d2 = v.z - mu, d3 = v.w - mu;
    float ss = d0*d0 + d1*d1 + d2*d2 + d3*d3;
    #pragma unroll
    for (int o = 16; o; o >>= 1) ss += __shfl_xor_sync(0xffffffffu, ss, o);
    if ((t & 31) == 0) sh[t >> 5] = ss;
    __syncthreads();
    float var = sh[0];
    #pragma unroll
    for (int i = 1; i < 8; i++) var += sh[i];
    var *= (1.f / 1024.f);
    __syncthreads();

    float rstd = rsqrtf(var + EPSF);
    float4 g = gamma[t], b = beta[t];
    float y0 = d0 * rstd * g.x + b.x;
    float y1 = d1 * rstd * g.y + b.y;
    float y2 = d2 * rstd * g.z + b.z;
    float y3 = d3 * rstd * g.w + b.w;

    float am = fmaxf(fmaxf(fabsf(y0), fabsf(y1)), fmaxf(fabsf(y2), fabsf(y3)));
    #pragma unroll
    for (int o = 16; o; o >>= 1) am = fmaxf(am, __shfl_xor_sync(0xffffffffu, am, o));
    if ((t & 31) == 0) sh[t >> 5] = am;
    __syncthreads();
    float amax = sh[0];
    #pragma unroll
    for (int i = 1; i < 8; i++) amax = fmaxf(amax, sh[i]);

    amax = fmaxf(amax, EPSF);
    float sc = 127.f / amax;
    __half2 h0 = __floats2half2_rn(rintf(fminf(fmaxf(y0 * sc, -127.f), 127.f)),
                                   rintf(fminf(fmaxf(y1 * sc, -127.f), 127.f)));
    __half2 h1 = __floats2half2_rn(rintf(fminf(fmaxf(y2 * sc, -127.f), 127.f)),
                                   rintf(fminf(fmaxf(y3 * sc, -127.f), 127.f)));
    __half2* dst = (__half2*)g_a1h;
    dst[(size_t)row * 512 + 2 * t]     = h0;
    dst[(size_t)row * 512 + 2 * t + 1] = h1;
    if (t == 0) g_dqa1[row] = amax * (1.f / 127.f);
}

// 2 float4 per thread (32B); coalesced per-warp 1KB segments.
__global__ void quant_h_k() {
    size_t gid = (size_t)blockIdx.x * blockDim.x + threadIdx.x;
    size_t i = gid * 2;
    const float4* __restrict__ src = (const float4*)g_h;
    __half2* __restrict__ dst = (__half2*)g_a2h;
    #pragma unroll
    for (int u = 0; u < 2; u++) {
        size_t idx = i + u;
        int row = (int)(idx >> 10);                  // FF/4 = 1024 float4 per row
        float s = 127.f / fmaxf(__uint_as_float(g_hmax[row]), EPSF);
        float4 v = src[idx];
        __half2 h0 = __floats2half2_rn(rintf(fminf(fmaxf(v.x * s, -127.f), 127.f)),
                                       rintf(fminf(fmaxf(v.y * s, -127.f), 127.f)));
        __half2 h1 = __floats2half2_rn(rintf(fminf(fmaxf(v.z * s, -127.f), 127.f)),
                                       rintf(fminf(fmaxf(v.w * s, -127.f), 127.f)));
        dst[2 * idx]     = h0;
        dst[2 * idx + 1] = h1;
    }
}

// ======================= launcher =======================
extern "C" void kernel_launch(void* const* d_in, const int* in_sizes, int n_in,
                              void* d_out, int out_size) {
    const float* x     = (const float*)d_in[0];   // [8,2048,1024]
    const float* mask  = (const float*)d_in[1];   // [8,2048,1]
    const float* gamma = (const float*)d_in[2];   // [1024]
    const float* beta  = (const float*)d_in[3];   // [1024]
    const float* w1    = (const float*)d_in[4];   // [4096,1024]
    const float* b1    = (const float*)d_in[5];   // [4096]
    const float* w2    = (const float*)d_in[6];   // [1024,4096]
    const float* b2    = (const float*)d_in[7];   // [1024]
    float* out = (float*)d_out;

    const int wn4 = (FF * DIM) / 4;               // 1,048,576
    const int GEMM_SMEM = 3 * 128 * 128 * 2;      // 98304 = 96KB
    cudaFuncSetAttribute(gemm_f16_k<1>, cudaFuncAttributeMaxDynamicSharedMemorySize, GEMM_SMEM);
    cudaFuncSetAttribute(gemm_f16_k<2>, cudaFuncAttributeMaxDynamicSharedMemorySize, GEMM_SMEM);

    // weights: absmax -> quantize to fp16 ints (idempotent across graph replays)
    absmax_both_k<<<dim3(1024, 2), 256>>>((const float4*)w1, (const float4*)w2, wn4);
    quantw_both_k<<<dim3(wn4 / 256, 2), 256>>>((const float4*)w1, (const float4*)w2, wn4);

    // LN + per-token act quant -> fp16 ints
    ln_quant_k<<<N_TOK, 256>>>((const float4*)x, (const float4*)gamma, (const float4*)beta);

    // GEMM1 + swish + row absmax
    gemm_f16_k<1><<<dim3(FF / 128, N_TOK / 128), 128, GEMM_SMEM>>>(b1, nullptr, nullptr, nullptr);

    // quantize h -> fp16 ints
    quant_h_k<<<(N_TOK * (FF / 4)) / 512, 256>>>();

    // GEMM2 + residual
    gemm_f16_k<2><<<dim3(DIM / 128, N_TOK / 128), 128, GEMM_SMEM>>>(b2, x, mask, out);
}

// round 8
// speedup vs baseline: 1.2427x; 1.0424x over previous
#include <cuda_runtime.h>
#include <cuda_fp16.h>
#include <cstdint>
#include <math.h>

#define EPSF 1e-5f

static const int N_TOK = 16384;   // B*T = 8*2048
static const int DIM   = 1024;
static const int FF    = 4096;

// ---------------- scratch (device globals; allocation-free) ----------------
__device__ __half   g_w1h[(size_t)FF * DIM];      // 8 MB  (quantized ints as half)
__device__ __half   g_w2h[(size_t)DIM * FF];      // 8 MB
__device__ __half   g_a1h[(size_t)N_TOK * DIM];   // 32 MB
__device__ __half   g_a2h[(size_t)N_TOK * FF];    // 128 MB
__device__ float    g_h  [(size_t)N_TOK * FF];    // 256 MB
__device__ float    g_dqa1[N_TOK];
__device__ unsigned g_hmax[N_TOK];                // float bits, idempotent max
__device__ unsigned g_wmax[2];                    // float bits

// ---------------- small PTX helpers ----------------
__device__ __forceinline__ void cp16(uint32_t dst, const void* src) {
    asm volatile("cp.async.cg.shared.global [%0], [%1], 16;\n" :: "r"(dst), "l"(src));
}
__device__ __forceinline__ void cp_commit() { asm volatile("cp.async.commit_group;\n"); }
template<int N> __device__ __forceinline__ void cp_wait() {
    asm volatile("cp.async.wait_group %0;\n" :: "n"(N));
}
__device__ __forceinline__ void ldsm4(uint32_t& r0, uint32_t& r1, uint32_t& r2, uint32_t& r3,
                                      uint32_t addr) {
    asm volatile("ldmatrix.sync.aligned.m8n8.x4.shared.b16 {%0,%1,%2,%3}, [%4];"
                 : "=r"(r0), "=r"(r1), "=r"(r2), "=r"(r3) : "r"(addr));
}

// ======================= fp16 GEMM via mma.sync m16n8k16 =======================
// Operands are quantized integers stored as fp16 (exact); accumulate fp32.
// BM=128, BN=128, BK=64 (128B rows). 256 threads = 8 warps as 2(m) x 4(n),
// warp tile 64x32. 3-stage cp.async pipeline, 96KB smem/CTA, 2 CTAs/SM
// (16 warps/SM = 4 per SMSP for latency hiding).
// Smem swizzle: 16B chunk' = chunk ^ (row & 7)  (8 chunks per 128B row).
//
// EPI==1: g_h = swish(dq(a1 @ w1^T) + b1), row absmax -> g_hmax
// EPI==2: out = x + 0.5*mask*(dq(a2 @ w2^T) + b2)
template<int EPI>
__launch_bounds__(256, 2)
__global__ void gemm_f16_k(const float* __restrict__ bias,
                           const float* __restrict__ xres,
                           const float* __restrict__ mask,
                           float* __restrict__ out) {
    constexpr int K  = (EPI == 1) ? DIM : FF;        // elements (halves)
    constexpr int KT = K / 64;                       // BK=64 slabs
    constexpr int STAGE = 128 * 128 * 2;             // A 16KB + B 16KB = 32KB

    const __half* __restrict__ A  = (EPI == 1) ? g_a1h : g_a2h;
    const __half* __restrict__ Bw = (EPI == 1) ? g_w1h : g_w2h;

    extern __shared__ int8_t sm[];                   // 3 * 32KB

    const int tid  = threadIdx.x;
    const int lane = tid & 31;
    const int warp = tid >> 5;
    const int wm   = warp >> 2;                      // 0..1
    const int wn   = warp & 3;                       // 0..3
    const int bm   = blockIdx.y * 128;
    const int bn   = blockIdx.x * 128;

    float acc[4][4][4];
    #pragma unroll
    for (int mi = 0; mi < 4; mi++)
        #pragma unroll
        for (int ni = 0; ni < 4; ni++)
            #pragma unroll
            for (int j = 0; j < 4; j++) acc[mi][ni][j] = 0.f;

    auto ld_stage = [&](int stg, int kt) {
        uint32_t ab = (uint32_t)__cvta_generic_to_shared(sm + stg * STAGE);
        uint32_t bb = ab + 128 * 128;
        #pragma unroll
        for (int i = 0; i < 4; i++) {                // A: 1024 chunks of 16B
            int c = tid + i * 256;
            int row = c >> 3, ch = c & 7;
            uint32_t dst = ab + row * 128 + ((ch ^ (row & 7)) << 4);
            cp16(dst, (const int8_t*)A + (size_t)(bm + row) * (K * 2) + kt * 128 + ch * 16);
        }
        #pragma unroll
        for (int i = 0; i < 4; i++) {                // B: 1024 chunks of 16B
            int c = tid + i * 256;
            int row = c >> 3, ch = c & 7;
            uint32_t dst = bb + row * 128 + ((ch ^ (row & 7)) << 4);
            cp16(dst, (const int8_t*)Bw + (size_t)(bn + row) * (K * 2) + kt * 128 + ch * 16);
        }
        cp_commit();
    };

    ld_stage(0, 0);
    ld_stage(1, 1);

    for (int kt = 0; kt < KT; ++kt) {
        if (kt + 2 < KT) { cp_wait<1>(); } else { cp_wait<0>(); }
        __syncthreads();
        if (kt + 2 < KT) ld_stage((kt + 2) % 3, kt + 2);

        uint32_t abase = (uint32_t)__cvta_generic_to_shared(sm + (kt % 3) * STAGE);
        uint32_t bbase = abase + 128 * 128;

        #pragma unroll
        for (int ks = 0; ks < 4; ++ks) {             // four k16 steps per slab
            uint32_t af[4][4], bf[4][2];
            #pragma unroll
            for (int mi = 0; mi < 4; mi++) {         // A: 64 rows x k16
                int row = wm * 64 + mi * 16 + (lane & 15);
                int ch  = 2 * ks + (lane >> 4);
                uint32_t a = abase + row * 128 + ((ch ^ (row & 7)) << 4);
                ldsm4(af[mi][0], af[mi][1], af[mi][2], af[mi][3], a);
            }
            #pragma unroll
            for (int p = 0; p < 2; p++) {            // B: 32 rows x k16
                int row = wn * 32 + p * 16 + ((lane >> 4) << 3) + (lane & 7);
                int ch  = 2 * ks + ((lane >> 3) & 1);
                uint32_t a = bbase + row * 128 + ((ch ^ (row & 7)) << 4);
                ldsm4(bf[2 * p][0], bf[2 * p][1], bf[2 * p + 1][0], bf[2 * p + 1][1], a);
            }
            #pragma unroll
            for (int mi = 0; mi < 4; mi++)
                #pragma unroll
                for (int ni = 0; ni < 4; ni++)
                    asm volatile(
                        "mma.sync.aligned.m16n8k16.row.col.f32.f16.f16.f32 "
                        "{%0,%1,%2,%3}, {%4,%5,%6,%7}, {%8,%9}, {%0,%1,%2,%3};\n"
                        : "+f"(acc[mi][ni][0]), "+f"(acc[mi][ni][1]),
                          "+f"(acc[mi][ni][2]), "+f"(acc[mi][ni][3])
                        : "r"(af[mi][0]), "r"(af[mi][1]), "r"(af[mi][2]), "r"(af[mi][3]),
                          "r"(bf[ni][0]), "r"(bf[ni][1]));
        }
    }

    // ---------------- epilogue (8-warp 2x4, warp tile 64x32) ----------------
    const float dqw = fmaxf(__uint_as_float(g_wmax[EPI - 1]), EPSF) * (1.f / 127.f);

    if (EPI == 1) {
        #pragma unroll
        for (int mi = 0; mi < 4; mi++) {
            #pragma unroll
            for (int half = 0; half < 2; ++half) {
                int row = bm + wm * 64 + mi * 16 + (lane >> 2) + half * 8;
                float f = g_dqa1[row] * dqw;
                float rmax = 0.f;
                #pragma unroll
                for (int ni = 0; ni < 4; ni++) {
                    #pragma unroll
                    for (int j = 0; j < 2; j++) {
                        int col = bn + wn * 32 + ni * 8 + (lane & 3) * 2 + j;
                        float v  = acc[mi][ni][half * 2 + j] * f + __ldg(&bias[col]);
                        float hv = v / (1.f + __expf(-v));     // v * sigmoid(v)
                        g_h[(size_t)row * FF + col] = hv;
                        rmax = fmaxf(rmax, fabsf(hv));
                    }
                }
                rmax = fmaxf(rmax, __shfl_xor_sync(0xffffffffu, rmax, 1));
                rmax = fmaxf(rmax, __shfl_xor_sync(0xffffffffu, rmax, 2));
                if ((lane & 3) == 0) atomicMax(&g_hmax[row], __float_as_uint(rmax));
            }
        }
    } else {
        #pragma unroll
        for (int mi = 0; mi < 4; mi++) {
            #pragma unroll
            for (int half = 0; half < 2; ++half) {
                int row = bm + wm * 64 + mi * 16 + (lane >> 2) + half * 8;
                float f  = fmaxf(__uint_as_float(g_hmax[row]), EPSF) * (1.f / 127.f) * dqw;
                float mk = mask[row];
                #pragma unroll
                for (int ni = 0; ni < 4; ni++) {
                    #pragma unroll
                    for (int j = 0; j < 2; j++) {
                        int col = bn + wn * 32 + ni * 8 + (lane & 3) * 2 + j;
                        float v = acc[mi][ni][half * 2 + j] * f + __ldg(&bias[col]);
                        out[(size_t)row * DIM + col] =
                            xres[(size_t)row * DIM + col] + 0.5f * v * mk;
                    }
                }
            }
        }
    }
}

// ======================= elementwise kernels =======================
__global__ void absmax_both_k(const float4* __restrict__ w1,
                              const float4* __restrict__ w2, int n4) {
    const int wi = blockIdx.y;
    const float4* __restrict__ x = wi ? w2 : w1;
    float m = 0.f;
    for (int i = blockIdx.x * blockDim.x + threadIdx.x; i < n4; i += gridDim.x * blockDim.x) {
        float4 v = x[i];
        m = fmaxf(m, fmaxf(fmaxf(fabsf(v.x), fabsf(v.y)), fmaxf(fabsf(v.z), fabsf(v.w))));
    }
    #pragma unroll
    for (int o = 16; o; o >>= 1) m = fmaxf(m, __shfl_xor_sync(0xffffffffu, m, o));
    __shared__ float sh[32];
    if ((threadIdx.x & 31) == 0) sh[threadIdx.x >> 5] = m;
    __syncthreads();
    if (threadIdx.x < 32) {
        m = (threadIdx.x < (blockDim.x >> 5)) ? sh[threadIdx.x] : 0.f;
        #pragma unroll
        for (int o = 16; o; o >>= 1) m = fmaxf(m, __shfl_xor_sync(0xffffffffu, m, o));
        if (threadIdx.x == 0) atomicMax(&g_wmax[wi], __float_as_uint(m));
    }
}

__global__ void quantw_both_k(const float4* __restrict__ w1,
                              const float4* __restrict__ w2, int n4) {
    const int wi = blockIdx.y;
    const float4* __restrict__ w = wi ? w2 : w1;
    int i = blockIdx.x * blockDim.x + threadIdx.x;
    if (i >= n4) return;
    float s = 127.f / fmaxf(__uint_as_float(g_wmax[wi]), EPSF);
    float4 v = w[i];
    __half2 h0 = __floats2half2_rn(rintf(fminf(fmaxf(v.x * s, -127.f), 127.f)),
                                   rintf(fminf(fmaxf(v.y * s, -127.f), 127.f)));
    __half2 h1 = __floats2half2_rn(rintf(fminf(fmaxf(v.z * s, -127.f), 127.f)),
                                   rintf(fminf(fmaxf(v.w * s, -127.f), 127.f)));
    __half2* dst = (__half2*)(wi ? g_w2h : g_w1h);
    dst[2 * i]     = h0;
    dst[2 * i + 1] = h1;
}

__global__ void ln_quant_k(const float4* __restrict__ x,
                           const float4* __restrict__ gamma,
                           const float4* __restrict__ beta) {
    const int row = blockIdx.x;
    const int t   = threadIdx.x;           // 256 threads, D/4 = 256 float4
    __shared__ float sh[8];

    float4 v = x[(size_t)row * 256 + t];
    float s = v.x + v.y + v.z + v.w;
    #pragma unroll
    for (int o = 16; o; o >>= 1) s += __shfl_xor_sync(0xffffffffu, s, o);
    if ((t & 31) == 0) sh[t >> 5] = s;
    __syncthreads();
    float mu = sh[0];
    #pragma unroll
    for (int i = 1; i < 8; i++) mu += sh[i];
    mu *= (1.f / 1024.f);
    __syncthreads();

    float d0 = v.x - mu, d1 = v.y - mu, d2 = v.z - mu, d3 = v.w - mu;
    float ss = d0*d0 + d1*d1 + d2*d2 + d3*d3;
    #pragma unroll
    for (int o = 16; o; o >>= 1) ss += __shfl_xor_sync(0xffffffffu, ss, o);
    if ((t & 31) == 0) sh[t >> 5] = ss;
    __syncthreads();
    float var = sh[0];
    #pragma unroll
    for (int i = 1; i < 8; i++) var += sh[i];
    var *= (1.f / 1024.f);
    __syncthreads();

    float rstd = rsqrtf(var + EPSF);
    float4 g = gamma[t], b = beta[t];
    float y0 = d0 * rstd * g.x + b.x;
    float y1 = d1 * rstd * g.y + b.y;
    float y2 = d2 * rstd * g.z + b.z;
    float y3 = d3 * rstd * g.w + b.w;

    float am = fmaxf(fmaxf(fabsf(y0), fabsf(y1)), fmaxf(fabsf(y2), fabsf(y3)));
    #pragma unroll
    for (int o = 16; o; o >>= 1) am = fmaxf(am, __shfl_xor_sync(0xffffffffu, am, o));
    if ((t & 31) == 0) sh[t >> 5] = am;
    __syncthreads();
    float amax = sh[0];
    #pragma unroll
    for (int i = 1; i < 8; i++) amax = fmaxf(amax, sh[i]);

    amax = fmaxf(amax, EPSF);
    float sc = 127.f / amax;
    __half2 h0 = __floats2half2_rn(rintf(fminf(fmaxf(y0 * sc, -127.f), 127.f)),
                                   rintf(fminf(fmaxf(y1 * sc, -127.f), 127.f)));
    __half2 h1 = __floats2half2_rn(rintf(fminf(fmaxf(y2 * sc, -127.f), 127.f)),
                                   rintf(fminf(fmaxf(y3 * sc, -127.f), 127.f)));
    __half2* dst = (__half2*)g_a1h;
    dst[(size_t)row * 512 + 2 * t]     = h0;
    dst[(size_t)row * 512 + 2 * t + 1] = h1;
    if (t == 0) g_dqa1[row] = amax * (1.f / 127.f);
}

// 2 float4 per thread (32B); coalesced per-warp 1KB segments.
__global__ void quant_h_k() {
    size_t gid = (size_t)blockIdx.x * blockDim.x + threadIdx.x;
    size_t i = gid * 2;
    const float4* __restrict__ src = (const float4*)g_h;
    __half2* __restrict__ dst = (__half2*)g_a2h;
    #pragma unroll
    for (int u = 0; u < 2; u++) {
        size_t idx = i + u;
        int row = (int)(idx >> 10);                  // FF/4 = 1024 float4 per row
        float s = 127.f / fmaxf(__uint_as_float(g_hmax[row]), EPSF);
        float4 v = src[idx];
        __half2 h0 = __floats2half2_rn(rintf(fminf(fmaxf(v.x * s, -127.f), 127.f)),
                                       rintf(fminf(fmaxf(v.y * s, -127.f), 127.f)));
        __half2 h1 = __floats2half2_rn(rintf(fminf(fmaxf(v.z * s, -127.f), 127.f)),
                                       rintf(fminf(fmaxf(v.w * s, -127.f), 127.f)));
        dst[2 * idx]     = h0;
        dst[2 * idx + 1] = h1;
    }
}

// ======================= launcher =======================
extern "C" void kernel_launch(void* const* d_in, const int* in_sizes, int n_in,
                              void* d_out, int out_size) {
    const float* x     = (const float*)d_in[0];   // [8,2048,1024]
    const float* mask  = (const float*)d_in[1];   // [8,2048,1]
    const float* gamma = (const float*)d_in[2];   // [1024]
    const float* beta  = (const float*)d_in[3];   // [1024]
    const float* w1    = (const float*)d_in[4];   // [4096,1024]
    const float* b1    = (const float*)d_in[5];   // [4096]
    const float* w2    = (const float*)d_in[6];   // [1024,4096]
    const float* b2    = (const float*)d_in[7];   // [1024]
    float* out = (float*)d_out;

    const int wn4 = (FF * DIM) / 4;               // 1,048,576
    const int GEMM_SMEM = 3 * 128 * 128 * 2;      // 98304 = 96KB
    cudaFuncSetAttribute(gemm_f16_k<1>, cudaFuncAttributeMaxDynamicSharedMemorySize, GEMM_SMEM);
    cudaFuncSetAttribute(gemm_f16_k<2>, cudaFuncAttributeMaxDynamicSharedMemorySize, GEMM_SMEM);

    // weights: absmax -> quantize to fp16 ints (idempotent across graph replays)
    absmax_both_k<<<dim3(1024, 2), 256>>>((const float4*)w1, (const float4*)w2, wn4);
    quantw_both_k<<<dim3(wn4 / 256, 2), 256>>>((const float4*)w1, (const float4*)w2, wn4);

    // LN + per-token act quant -> fp16 ints
    ln_quant_k<<<N_TOK, 256>>>((const float4*)x, (const float4*)gamma, (const float4*)beta);

    // GEMM1 + swish + row absmax
    gemm_f16_k<1><<<dim3(FF / 128, N_TOK / 128), 256, GEMM_SMEM>>>(b1, nullptr, nullptr, nullptr);

    // quantize h -> fp16 ints
    quant_h_k<<<(N_TOK * (FF / 4)) / 512, 256>>>();

    // GEMM2 + residual
    gemm_f16_k<2><<<dim3(DIM / 128, N_TOK / 128), 256, GEMM_SMEM>>>(b2, x, mask, out);
}